// round 13
// baseline (speedup 1.0000x reference)
#include <cuda_runtime.h>
#include <cuda_fp16.h>
#include <cstdint>

#define N_NODES 100000
#define FEAT 64
#define OUT_DIM 2

// Per-node projected message m = h @ W1, stored fp16x2 (400 KB, L2/L1 resident)
__device__ __half2 g_m[N_NODES];

// ---------------------------------------------------------------------------
// Fused node kernel: 444 blocks x 512 thr, __launch_bounds__(512,3) -> 42-reg
// budget (the old (1024,2) capped at 32 regs and likely spilled the x4 body).
//  - iteration-0 pos/vel loads issued BEFORE the fold (overlap DRAM latency
//    with the fold's shuffle chains)
//  - software-pipelined main loop (prefetch next quad before storing current)
//  - warp-per-node x4, multi-value butterfly: 6 shuffles per node
// ---------------------------------------------------------------------------
__global__ __launch_bounds__(512, 3)
void node_kernel(const float* __restrict__ pos,
                 const float* __restrict__ vel,
                 const float* __restrict__ W_rel,
                 const float* __restrict__ b_rel,
                 const float* __restrict__ W_root,
                 const float* __restrict__ W_pred,
                 const float* __restrict__ b_pred,
                 float* __restrict__ out) {
    __shared__ float4 sW[FEAT];       // (W1[f][0], W1[f][1], W2[f][0], W2[f][1])
    __shared__ float  sbias[OUT_DIM];

    int t    = threadIdx.x;
    int warp = t >> 5;                // 0..15
    int lane = t & 31;

    // ---- prefetch iteration 0 (independent of the fold) ----
    int wg    = blockIdx.x * 16 + warp;
    int total = gridDim.x * 16;       // 7104 warps
    int n0    = wg * 4;

    float P[4], V[4];
    if (n0 < N_NODES) {               // N_NODES % 4 == 0 -> whole quad valid
        #pragma unroll
        for (int j = 0; j < 4; ++j) P[j] = __ldcs(pos + (n0 + j) * 32 + lane);
        #pragma unroll
        for (int j = 0; j < 4; ++j) V[j] = __ldcs(vel + (n0 + j) * 32 + lane);
    }

    // ---- fold: 16 warps x 8 (k,o)-pairs = 128 entries ----
    #pragma unroll
    for (int i = 0; i < 8; ++i) {
        int p = warp * 8 + i;
        int k = p >> 1;
        int o = p & 1;
        float wp0 = W_pred[lane * OUT_DIM + o];
        float wp1 = W_pred[(lane + 32) * OUT_DIM + o];
        float s1 = W_rel [k * FEAT + lane] * wp0 + W_rel [k * FEAT + lane + 32] * wp1;
        float s2 = W_root[k * FEAT + lane] * wp0 + W_root[k * FEAT + lane + 32] * wp1;
        #pragma unroll
        for (int off = 16; off > 0; off >>= 1) {
            s1 += __shfl_xor_sync(0xffffffffu, s1, off);
            s2 += __shfl_xor_sync(0xffffffffu, s2, off);
        }
        if (lane == 0) {
            float* w = (float*)&sW[k];
            w[o]     = s1;
            w[2 + o] = s2;
        }
    }
    if (warp < OUT_DIM) {
        int o = warp;
        float bb = b_rel[lane]      * W_pred[lane * OUT_DIM + o]
                 + b_rel[lane + 32] * W_pred[(lane + 32) * OUT_DIM + o];
        #pragma unroll
        for (int off = 16; off > 0; off >>= 1)
            bb += __shfl_xor_sync(0xffffffffu, bb, off);
        if (lane == 0) sbias[o] = bb + b_pred[o];
    }
    __syncthreads();

    float4 wpk = sW[lane];            // weights for pos feature `lane`
    float4 wvk = sW[32 + lane];       // weights for vel feature `lane+32`
    float bias0 = sbias[0], bias1 = sbias[1];

    bool laneSel = (lane & 7) == 0;   // lanes 0,8,16,24 write results
    bool isM     = (lane & 8) == 0;   // 0,16 -> g_m ; 8,24 -> out
    int  hi      = lane >> 4;         // component 0 or 1

    __half* gm_h = (__half*)g_m;

    // ---- software-pipelined main loop ----
    while (n0 < N_NODES) {
        float y[4];
        #pragma unroll
        for (int j = 0; j < 4; ++j) {
            float m0 = P[j] * wpk.x + V[j] * wvk.x;
            float m1 = P[j] * wpk.y + V[j] * wvk.y;
            float r0 = P[j] * wpk.z + V[j] * wvk.z;
            float r1 = P[j] * wpk.w + V[j] * wvk.w;

            // multi-value butterfly: 6 shuffles reduce all 4 accumulators
            float xA = (lane & 16) ? m1 : m0;
            float gA = (lane & 16) ? m0 : m1;
            xA += __shfl_xor_sync(0xffffffffu, gA, 16);
            float xB = (lane & 16) ? r1 : r0;
            float gB = (lane & 16) ? r0 : r1;
            xB += __shfl_xor_sync(0xffffffffu, gB, 16);
            float yy = (lane & 8) ? xB : xA;
            float gg = (lane & 8) ? xA : xB;
            yy += __shfl_xor_sync(0xffffffffu, gg, 8);
            yy += __shfl_xor_sync(0xffffffffu, yy, 4);
            yy += __shfl_xor_sync(0xffffffffu, yy, 2);
            yy += __shfl_xor_sync(0xffffffffu, yy, 1);
            y[j] = yy;
        }

        // prefetch next quad while y-stores retire
        int n1 = n0 + total * 4;
        if (n1 < N_NODES) {
            #pragma unroll
            for (int j = 0; j < 4; ++j) P[j] = __ldcs(pos + (n1 + j) * 32 + lane);
            #pragma unroll
            for (int j = 0; j < 4; ++j) V[j] = __ldcs(vel + (n1 + j) * 32 + lane);
        }

        if (laneSel) {
            #pragma unroll
            for (int j = 0; j < 4; ++j) {
                int n = n0 + j;
                if (isM) gm_h[2 * n + hi] = __float2half(y[j]);
                else     out[2 * n + hi] = y[j] + (hi ? bias1 : bias0);
            }
        }
        n0 = n1;
    }
}

// ---------------------------------------------------------------------------
// Edge kernel: EXACT R12 (proven 29.3us). PDL sync at top (no state held
// across it -> 32 regs), 8 edges/thread single pass, fp16x2 gathers, f32 REDs.
// ---------------------------------------------------------------------------
__device__ __forceinline__ void red_v2(float* addr, float2 v) {
    asm volatile("red.global.add.v2.f32 [%0], {%1, %2};"
                 :: "l"(addr), "f"(v.x), "f"(v.y) : "memory");
}

__global__ void edge_kernel(const int* __restrict__ src,
                            const int* __restrict__ dst,
                            float* __restrict__ out,
                            int n_edges) {
    cudaGridDependencySynchronize();

    int t = blockIdx.x * blockDim.x + threadIdx.x;
    int base = t * 8;
    if (base + 7 < n_edges) {
        int4 s0 = __ldcs((const int4*)(src + base));
        int4 s1 = __ldcs((const int4*)(src + base + 4));
        int4 d0 = __ldcs((const int4*)(dst + base));
        int4 d1 = __ldcs((const int4*)(dst + base + 4));
        float2 a0 = __half22float2(g_m[s0.x]);
        float2 a1 = __half22float2(g_m[s0.y]);
        float2 a2 = __half22float2(g_m[s0.z]);
        float2 a3 = __half22float2(g_m[s0.w]);
        float2 b0 = __half22float2(g_m[s1.x]);
        float2 b1 = __half22float2(g_m[s1.y]);
        float2 b2 = __half22float2(g_m[s1.z]);
        float2 b3 = __half22float2(g_m[s1.w]);
        red_v2(out + 2 * d0.x, a0);
        red_v2(out + 2 * d0.y, a1);
        red_v2(out + 2 * d0.z, a2);
        red_v2(out + 2 * d0.w, a3);
        red_v2(out + 2 * d1.x, b0);
        red_v2(out + 2 * d1.y, b1);
        red_v2(out + 2 * d1.z, b2);
        red_v2(out + 2 * d1.w, b3);
    } else {
        for (int i = base; i < n_edges; ++i) {
            float2 mm = __half22float2(g_m[src[i]]);
            red_v2(out + 2 * dst[i], mm);
        }
    }
}

// ---------------------------------------------------------------------------
// Launch
// Inputs (metadata order): pos, vel, edge_index, W_rel, b_rel, W_root, W_pred, b_pred
// ---------------------------------------------------------------------------
extern "C" void kernel_launch(void* const* d_in, const int* in_sizes, int n_in,
                              void* d_out, int out_size) {
    const float* pos    = (const float*)d_in[0];
    const float* vel    = (const float*)d_in[1];
    const int*   eidx   = (const int*)  d_in[2];
    const float* W_rel  = (const float*)d_in[3];
    const float* b_rel  = (const float*)d_in[4];
    const float* W_root = (const float*)d_in[5];
    const float* W_pred = (const float*)d_in[6];
    const float* b_pred = (const float*)d_in[7];
    float* out = (float*)d_out;

    const int n_edges = in_sizes[2] / 2;          // 3.2M
    const int* src = eidx;
    const int* dst = eidx + n_edges;

    node_kernel<<<444, 512>>>(pos, vel, W_rel, b_rel, W_root,
                              W_pred, b_pred, out);

    int n_thr    = (n_edges + 7) / 8;
    int n_blocks = (n_thr + 255) / 256;

    cudaLaunchConfig_t cfg = {};
    cfg.gridDim  = dim3(n_blocks, 1, 1);
    cfg.blockDim = dim3(256, 1, 1);
    cudaLaunchAttribute attr[1];
    attr[0].id = cudaLaunchAttributeProgrammaticStreamSerialization;
    attr[0].val.programmaticStreamSerializationAllowed = 1;
    cfg.attrs    = attr;
    cfg.numAttrs = 1;
    cudaLaunchKernelEx(&cfg, edge_kernel, src, dst, out, n_edges);
}

// round 14
// speedup vs baseline: 1.0117x; 1.0117x over previous
#include <cuda_runtime.h>
#include <cuda_fp16.h>
#include <cstdint>

#define N_NODES 100000
#define FEAT 64
#define OUT_DIM 2

// Per-node projected message m = h @ W1, stored fp16x2 (400 KB, L2/L1 resident)
__device__ __half2 g_m[N_NODES];

// ---------------------------------------------------------------------------
// Fused node kernel (296 blocks x 1024 thr, 2 blocks/SM) — exact R11/R12:
//  1) warp-cooperative weight fold (32 warps x 4 pairs)
//  2) warp-per-node x4 unroll, multi-value butterfly (6 shuffles per node)
// ---------------------------------------------------------------------------
__global__ __launch_bounds__(1024, 2)
void node_kernel(const float* __restrict__ pos,
                 const float* __restrict__ vel,
                 const float* __restrict__ W_rel,
                 const float* __restrict__ b_rel,
                 const float* __restrict__ W_root,
                 const float* __restrict__ W_pred,
                 const float* __restrict__ b_pred,
                 float* __restrict__ out) {
    __shared__ float4 sW[FEAT];       // (W1[f][0], W1[f][1], W2[f][0], W2[f][1])
    __shared__ float  sbias[OUT_DIM];

    int t    = threadIdx.x;
    int warp = t >> 5;                // 0..31
    int lane = t & 31;

    // ---- fold: 32 warps x 4 (k,o)-pairs ----
    #pragma unroll
    for (int i = 0; i < 4; ++i) {
        int p = warp * 4 + i;
        int k = p >> 1;
        int o = p & 1;
        float wp0 = W_pred[lane * OUT_DIM + o];
        float wp1 = W_pred[(lane + 32) * OUT_DIM + o];
        float s1 = W_rel [k * FEAT + lane] * wp0 + W_rel [k * FEAT + lane + 32] * wp1;
        float s2 = W_root[k * FEAT + lane] * wp0 + W_root[k * FEAT + lane + 32] * wp1;
        #pragma unroll
        for (int off = 16; off > 0; off >>= 1) {
            s1 += __shfl_xor_sync(0xffffffffu, s1, off);
            s2 += __shfl_xor_sync(0xffffffffu, s2, off);
        }
        if (lane == 0) {
            float* w = (float*)&sW[k];
            w[o]     = s1;
            w[2 + o] = s2;
        }
    }
    if (warp < OUT_DIM) {
        int o = warp;
        float bb = b_rel[lane]      * W_pred[lane * OUT_DIM + o]
                 + b_rel[lane + 32] * W_pred[(lane + 32) * OUT_DIM + o];
        #pragma unroll
        for (int off = 16; off > 0; off >>= 1)
            bb += __shfl_xor_sync(0xffffffffu, bb, off);
        if (lane == 0) sbias[o] = bb + b_pred[o];
    }
    __syncthreads();

    float4 wpk = sW[lane];            // weights for pos feature `lane`
    float4 wvk = sW[32 + lane];       // weights for vel feature `lane+32`
    float bias0 = sbias[0], bias1 = sbias[1];

    bool laneSel = (lane & 7) == 0;   // lanes 0,8,16,24 write results
    bool isM     = (lane & 8) == 0;   // 0,16 -> g_m ; 8,24 -> out
    int  hi      = lane >> 4;         // component 0 or 1

    __half* gm_h = (__half*)g_m;      // scalar half view for per-lane stores

    int wg    = blockIdx.x * 32 + warp;
    int total = gridDim.x * 32;       // 9472 warps

    for (int n0 = wg * 4; n0 < N_NODES; n0 += total * 4) {
        float P[4], V[4];
        #pragma unroll
        for (int j = 0; j < 4; ++j) P[j] = __ldcs(pos + (n0 + j) * 32 + lane);
        #pragma unroll
        for (int j = 0; j < 4; ++j) V[j] = __ldcs(vel + (n0 + j) * 32 + lane);

        float y[4];
        #pragma unroll
        for (int j = 0; j < 4; ++j) {
            float m0 = P[j] * wpk.x + V[j] * wvk.x;
            float m1 = P[j] * wpk.y + V[j] * wvk.y;
            float r0 = P[j] * wpk.z + V[j] * wvk.z;
            float r1 = P[j] * wpk.w + V[j] * wvk.w;

            float xA = (lane & 16) ? m1 : m0;
            float gA = (lane & 16) ? m0 : m1;
            xA += __shfl_xor_sync(0xffffffffu, gA, 16);
            float xB = (lane & 16) ? r1 : r0;
            float gB = (lane & 16) ? r0 : r1;
            xB += __shfl_xor_sync(0xffffffffu, gB, 16);
            float yy = (lane & 8) ? xB : xA;
            float gg = (lane & 8) ? xA : xB;
            yy += __shfl_xor_sync(0xffffffffu, gg, 8);
            yy += __shfl_xor_sync(0xffffffffu, yy, 4);
            yy += __shfl_xor_sync(0xffffffffu, yy, 2);
            yy += __shfl_xor_sync(0xffffffffu, yy, 1);
            y[j] = yy;
        }

        if (laneSel) {
            #pragma unroll
            for (int j = 0; j < 4; ++j) {
                int n = n0 + j;
                if (isM) gm_h[2 * n + hi] = __float2half(y[j]);
                else     out[2 * n + hi] = y[j] + (hi ? bias1 : bias0);
            }
        }
    }
}

// ---------------------------------------------------------------------------
// Edge kernel: same body as R12 (8 edges/thread, fp16x2 gathers, f32 v2 REDs,
// PDL sync at top). SINGLE CHANGE: block 256 -> 128 (3126 blocks) — finer
// tail granularity + higher resident-warp ceiling at 32 regs, with the proven
// 8-gather->8-RED MLP structure untouched.
// ---------------------------------------------------------------------------
__device__ __forceinline__ void red_v2(float* addr, float2 v) {
    asm volatile("red.global.add.v2.f32 [%0], {%1, %2};"
                 :: "l"(addr), "f"(v.x), "f"(v.y) : "memory");
}

__global__ __launch_bounds__(128)
void edge_kernel(const int* __restrict__ src,
                 const int* __restrict__ dst,
                 float* __restrict__ out,
                 int n_edges) {
    cudaGridDependencySynchronize();

    int t = blockIdx.x * blockDim.x + threadIdx.x;
    int base = t * 8;
    if (base + 7 < n_edges) {
        int4 s0 = __ldcs((const int4*)(src + base));
        int4 s1 = __ldcs((const int4*)(src + base + 4));
        int4 d0 = __ldcs((const int4*)(dst + base));
        int4 d1 = __ldcs((const int4*)(dst + base + 4));
        float2 a0 = __half22float2(g_m[s0.x]);
        float2 a1 = __half22float2(g_m[s0.y]);
        float2 a2 = __half22float2(g_m[s0.z]);
        float2 a3 = __half22float2(g_m[s0.w]);
        float2 b0 = __half22float2(g_m[s1.x]);
        float2 b1 = __half22float2(g_m[s1.y]);
        float2 b2 = __half22float2(g_m[s1.z]);
        float2 b3 = __half22float2(g_m[s1.w]);
        red_v2(out + 2 * d0.x, a0);
        red_v2(out + 2 * d0.y, a1);
        red_v2(out + 2 * d0.z, a2);
        red_v2(out + 2 * d0.w, a3);
        red_v2(out + 2 * d1.x, b0);
        red_v2(out + 2 * d1.y, b1);
        red_v2(out + 2 * d1.z, b2);
        red_v2(out + 2 * d1.w, b3);
    } else {
        for (int i = base; i < n_edges; ++i) {
            float2 mm = __half22float2(g_m[src[i]]);
            red_v2(out + 2 * dst[i], mm);
        }
    }
}

// ---------------------------------------------------------------------------
// Launch
// Inputs (metadata order): pos, vel, edge_index, W_rel, b_rel, W_root, W_pred, b_pred
// ---------------------------------------------------------------------------
extern "C" void kernel_launch(void* const* d_in, const int* in_sizes, int n_in,
                              void* d_out, int out_size) {
    const float* pos    = (const float*)d_in[0];
    const float* vel    = (const float*)d_in[1];
    const int*   eidx   = (const int*)  d_in[2];
    const float* W_rel  = (const float*)d_in[3];
    const float* b_rel  = (const float*)d_in[4];
    const float* W_root = (const float*)d_in[5];
    const float* W_pred = (const float*)d_in[6];
    const float* b_pred = (const float*)d_in[7];
    float* out = (float*)d_out;

    const int n_edges = in_sizes[2] / 2;          // 3.2M
    const int* src = eidx;
    const int* dst = eidx + n_edges;

    node_kernel<<<296, 1024>>>(pos, vel, W_rel, b_rel, W_root,
                               W_pred, b_pred, out);

    int n_thr    = (n_edges + 7) / 8;
    int n_blocks = (n_thr + 127) / 128;

    cudaLaunchConfig_t cfg = {};
    cfg.gridDim  = dim3(n_blocks, 1, 1);
    cfg.blockDim = dim3(128, 1, 1);
    cudaLaunchAttribute attr[1];
    attr[0].id = cudaLaunchAttributeProgrammaticStreamSerialization;
    attr[0].val.programmaticStreamSerializationAllowed = 1;
    cfg.attrs    = attr;
    cfg.numAttrs = 1;
    cudaLaunchKernelEx(&cfg, edge_kernel, src, dst, out, n_edges);
}

// round 15
// speedup vs baseline: 1.0443x; 1.0322x over previous
#include <cuda_runtime.h>
#include <cuda_fp16.h>
#include <cstdint>

#define N_NODES 100000
#define FEAT 64
#define OUT_DIM 2

// Per-node projected message m = h @ W1, stored fp16x2 (400 KB, L2/L1 resident)
__device__ __half2 g_m[N_NODES];

// ---------------------------------------------------------------------------
// Fused node kernel: 148 blocks x 1024 thr (ONE block/SM — leaves 1024 thread
// slots free so PDL edge blocks can co-reside and prefetch their indices).
// Fires the programmatic-launch trigger immediately so edge blocks spawn now.
// Body identical to proven R11/R12: warp fold + warp-per-node x4 multi-value
// butterfly. launch_bounds(1024,1) -> 64-reg budget (no 32-reg cap).
// ---------------------------------------------------------------------------
__global__ __launch_bounds__(1024, 1)
void node_kernel(const float* __restrict__ pos,
                 const float* __restrict__ vel,
                 const float* __restrict__ W_rel,
                 const float* __restrict__ b_rel,
                 const float* __restrict__ W_root,
                 const float* __restrict__ W_pred,
                 const float* __restrict__ b_pred,
                 float* __restrict__ out) {
    cudaTriggerProgrammaticLaunchCompletion();  // let edge blocks co-launch

    __shared__ float4 sW[FEAT];       // (W1[f][0], W1[f][1], W2[f][0], W2[f][1])
    __shared__ float  sbias[OUT_DIM];

    int t    = threadIdx.x;
    int warp = t >> 5;                // 0..31
    int lane = t & 31;

    // ---- fold: 32 warps x 4 (k,o)-pairs ----
    #pragma unroll
    for (int i = 0; i < 4; ++i) {
        int p = warp * 4 + i;
        int k = p >> 1;
        int o = p & 1;
        float wp0 = W_pred[lane * OUT_DIM + o];
        float wp1 = W_pred[(lane + 32) * OUT_DIM + o];
        float s1 = W_rel [k * FEAT + lane] * wp0 + W_rel [k * FEAT + lane + 32] * wp1;
        float s2 = W_root[k * FEAT + lane] * wp0 + W_root[k * FEAT + lane + 32] * wp1;
        #pragma unroll
        for (int off = 16; off > 0; off >>= 1) {
            s1 += __shfl_xor_sync(0xffffffffu, s1, off);
            s2 += __shfl_xor_sync(0xffffffffu, s2, off);
        }
        if (lane == 0) {
            float* w = (float*)&sW[k];
            w[o]     = s1;
            w[2 + o] = s2;
        }
    }
    if (warp < OUT_DIM) {
        int o = warp;
        float bb = b_rel[lane]      * W_pred[lane * OUT_DIM + o]
                 + b_rel[lane + 32] * W_pred[(lane + 32) * OUT_DIM + o];
        #pragma unroll
        for (int off = 16; off > 0; off >>= 1)
            bb += __shfl_xor_sync(0xffffffffu, bb, off);
        if (lane == 0) sbias[o] = bb + b_pred[o];
    }
    __syncthreads();

    float4 wpk = sW[lane];            // weights for pos feature `lane`
    float4 wvk = sW[32 + lane];       // weights for vel feature `lane+32`
    float bias0 = sbias[0], bias1 = sbias[1];

    bool laneSel = (lane & 7) == 0;   // lanes 0,8,16,24 write results
    bool isM     = (lane & 8) == 0;   // 0,16 -> g_m ; 8,24 -> out
    int  hi      = lane >> 4;         // component 0 or 1

    __half* gm_h = (__half*)g_m;

    int wg    = blockIdx.x * 32 + warp;
    int total = gridDim.x * 32;       // 4736 warps

    for (int n0 = wg * 4; n0 < N_NODES; n0 += total * 4) {
        float P[4], V[4];
        #pragma unroll
        for (int j = 0; j < 4; ++j) P[j] = __ldcs(pos + (n0 + j) * 32 + lane);
        #pragma unroll
        for (int j = 0; j < 4; ++j) V[j] = __ldcs(vel + (n0 + j) * 32 + lane);

        float y[4];
        #pragma unroll
        for (int j = 0; j < 4; ++j) {
            float m0 = P[j] * wpk.x + V[j] * wvk.x;
            float m1 = P[j] * wpk.y + V[j] * wvk.y;
            float r0 = P[j] * wpk.z + V[j] * wvk.z;
            float r1 = P[j] * wpk.w + V[j] * wvk.w;

            float xA = (lane & 16) ? m1 : m0;
            float gA = (lane & 16) ? m0 : m1;
            xA += __shfl_xor_sync(0xffffffffu, gA, 16);
            float xB = (lane & 16) ? r1 : r0;
            float gB = (lane & 16) ? r0 : r1;
            xB += __shfl_xor_sync(0xffffffffu, gB, 16);
            float yy = (lane & 8) ? xB : xA;
            float gg = (lane & 8) ? xA : xB;
            yy += __shfl_xor_sync(0xffffffffu, gg, 8);
            yy += __shfl_xor_sync(0xffffffffu, yy, 4);
            yy += __shfl_xor_sync(0xffffffffu, yy, 2);
            yy += __shfl_xor_sync(0xffffffffu, yy, 1);
            y[j] = yy;
        }

        if (laneSel) {
            #pragma unroll
            for (int j = 0; j < 4; ++j) {
                int n = n0 + j;
                if (isM) gm_h[2 * n + hi] = __float2half(y[j]);
                else     out[2 * n + hi] = y[j] + (hi ? bias1 : bias0);
            }
        }
    }
}

// ---------------------------------------------------------------------------
// Edge kernel (PDL secondary): pre-sync, prefetch this thread-group's index
// lines into L2 (zero registers held across the sync), overlapping the
// 25.6 MB index DRAM stream with the node kernel. Then grid-sync and run the
// proven body: 256 thr, 8 edges/thread, fp16x2 gathers, f32 v2 REDs.
// ---------------------------------------------------------------------------
__device__ __forceinline__ void red_v2(float* addr, float2 v) {
    asm volatile("red.global.add.v2.f32 [%0], {%1, %2};"
                 :: "l"(addr), "f"(v.x), "f"(v.y) : "memory");
}

__global__ __launch_bounds__(256)
void edge_kernel(const int* __restrict__ src,
                 const int* __restrict__ dst,
                 float* __restrict__ out,
                 int n_edges) {
    int t = blockIdx.x * blockDim.x + threadIdx.x;
    int base = t * 8;

    // L2 prefetch: one thread per 128B line (4 threads x 32B of indices)
    if ((t & 3) == 0 && base < n_edges) {
        asm volatile("prefetch.global.L2 [%0];" :: "l"(src + base));
        asm volatile("prefetch.global.L2 [%0];" :: "l"(dst + base));
    }

    cudaGridDependencySynchronize();

    if (base + 7 < n_edges) {
        int4 s0 = __ldcs((const int4*)(src + base));
        int4 s1 = __ldcs((const int4*)(src + base + 4));
        int4 d0 = __ldcs((const int4*)(dst + base));
        int4 d1 = __ldcs((const int4*)(dst + base + 4));
        float2 a0 = __half22float2(g_m[s0.x]);
        float2 a1 = __half22float2(g_m[s0.y]);
        float2 a2 = __half22float2(g_m[s0.z]);
        float2 a3 = __half22float2(g_m[s0.w]);
        float2 b0 = __half22float2(g_m[s1.x]);
        float2 b1 = __half22float2(g_m[s1.y]);
        float2 b2 = __half22float2(g_m[s1.z]);
        float2 b3 = __half22float2(g_m[s1.w]);
        red_v2(out + 2 * d0.x, a0);
        red_v2(out + 2 * d0.y, a1);
        red_v2(out + 2 * d0.z, a2);
        red_v2(out + 2 * d0.w, a3);
        red_v2(out + 2 * d1.x, b0);
        red_v2(out + 2 * d1.y, b1);
        red_v2(out + 2 * d1.z, b2);
        red_v2(out + 2 * d1.w, b3);
    } else {
        for (int i = base; i < n_edges; ++i) {
            float2 mm = __half22float2(g_m[src[i]]);
            red_v2(out + 2 * dst[i], mm);
        }
    }
}

// ---------------------------------------------------------------------------
// Launch
// Inputs (metadata order): pos, vel, edge_index, W_rel, b_rel, W_root, W_pred, b_pred
// ---------------------------------------------------------------------------
extern "C" void kernel_launch(void* const* d_in, const int* in_sizes, int n_in,
                              void* d_out, int out_size) {
    const float* pos    = (const float*)d_in[0];
    const float* vel    = (const float*)d_in[1];
    const int*   eidx   = (const int*)  d_in[2];
    const float* W_rel  = (const float*)d_in[3];
    const float* b_rel  = (const float*)d_in[4];
    const float* W_root = (const float*)d_in[5];
    const float* W_pred = (const float*)d_in[6];
    const float* b_pred = (const float*)d_in[7];
    float* out = (float*)d_out;

    const int n_edges = in_sizes[2] / 2;          // 3.2M
    const int* src = eidx;
    const int* dst = eidx + n_edges;

    // ONE block per SM: leaves room for edge blocks to co-reside via PDL
    node_kernel<<<148, 1024>>>(pos, vel, W_rel, b_rel, W_root,
                               W_pred, b_pred, out);

    int n_thr    = (n_edges + 7) / 8;
    int n_blocks = (n_thr + 255) / 256;

    cudaLaunchConfig_t cfg = {};
    cfg.gridDim  = dim3(n_blocks, 1, 1);
    cfg.blockDim = dim3(256, 1, 1);
    cudaLaunchAttribute attr[1];
    attr[0].id = cudaLaunchAttributeProgrammaticStreamSerialization;
    attr[0].val.programmaticStreamSerializationAllowed = 1;
    cfg.attrs    = attr;
    cfg.numAttrs = 1;
    cudaLaunchKernelEx(&cfg, edge_kernel, src, dst, out, n_edges);
}